// round 4
// baseline (speedup 1.0000x reference)
#include <cuda_runtime.h>
#include <cuda_bf16.h>

#define N_ATOMS   5000
#define N_EDGES   200000
#define N_TRIPLES 4000000
#define D_NODE    128
#define D_EDGE    128
#define N_BASIS   9

// Scratch (no allocations allowed)
__device__ float g_atoms[N_ATOMS * N_BASIS];        // sigmoid(node@W_atom+b)  [5000 x 9]
__device__ float g_new_bonds[N_EDGES * N_BASIS];    // segment sums            [200000 x 9]

// ---------------------------------------------------------------------------
// Kernel 0: zero the segment-sum accumulator
// ---------------------------------------------------------------------------
__global__ void zero_bonds_kernel() {
    int i = blockIdx.x * blockDim.x + threadIdx.x;
    const int n4 = (N_EDGES * N_BASIS) / 4;  // 450000
    if (i < n4) reinterpret_cast<float4*>(g_new_bonds)[i] = make_float4(0.f, 0.f, 0.f, 0.f);
}

// ---------------------------------------------------------------------------
// Kernel 1: atoms = sigmoid(node_feat @ W_atom + b_atom)   [5000 x 9]
// ---------------------------------------------------------------------------
__global__ void atoms_kernel(const float* __restrict__ node_feat,
                             const float* __restrict__ W_atom,
                             const float* __restrict__ b_atom) {
    int id = blockIdx.x * blockDim.x + threadIdx.x;
    if (id >= N_ATOMS * N_BASIS) return;
    int a = id / N_BASIS;
    int j = id % N_BASIS;
    float acc = b_atom[j];
    const float* nf = node_feat + a * D_NODE;
    #pragma unroll 8
    for (int k = 0; k < D_NODE; k++)
        acc = fmaf(nf[k], W_atom[k * N_BASIS + j], acc);
    g_atoms[id] = 1.0f / (1.0f + __expf(-acc));
}

// ---------------------------------------------------------------------------
// Kernel 2 (REWRITTEN): coalesced warp staging through shared memory.
//
// Warp handles 512 contiguous triples per iteration, in 4 passes of 128.
// Lane owns 4-triple groups at base + s*128 + lane*4 (contiguous -> register
// run-accumulation on sorted segment_ids still works; acc persists across
// passes AND warp-chunks, flushed only on segment change / thread exit).
//
// Staging: pass data (128 triples * 9 floats = 1152 floats) loaded as 9
// perfectly-coalesced float4 per lane into registers (double-buffered: LDG
// for pass s+1 overlaps compute of pass s), STS'd linearly into the warp's
// smem slot, then each lane reads its own 36 floats via LDS.
//
// smem: atoms fp32 table 180000 B + 11 warp slots * 4608 B = 230688 B.
// ---------------------------------------------------------------------------
#define TPB_T    352                         // 11 warps
#define GRID_T   148
#define NWARPS_T (GRID_T * (TPB_T / 32))     // 1628
#define WCHUNK   512                         // triples per warp-iteration
#define NWC      ((N_TRIPLES + WCHUNK - 1) / WCHUNK)   // 7813 (last has 256)
#define SLOT_F   1152                        // floats per warp slot
#define SMEM_T_BYTES ((N_ATOMS * N_BASIS + (TPB_T / 32) * SLOT_F) * 4)

__global__ __launch_bounds__(TPB_T) void triples_kernel(
    const float* __restrict__ three_basis,
    const int*   __restrict__ graph_dst,
    const int*   __restrict__ lg_dst,
    const int*   __restrict__ seg_ids) {

    extern __shared__ float smem[];
    float* s_atoms = smem;                               // 45000 floats
    float* slot = smem + N_ATOMS * N_BASIS + (threadIdx.x >> 5) * SLOT_F;

    for (int i = threadIdx.x; i < N_ATOMS * N_BASIS; i += TPB_T)
        s_atoms[i] = g_atoms[i];
    __syncthreads();

    const float4* tb4 = reinterpret_cast<const float4*>(three_basis);
    const int4*   lg4 = reinterpret_cast<const int4*>(lg_dst);
    const int4*   sg4 = reinterpret_cast<const int4*>(seg_ids);

    const int lane = threadIdx.x & 31;
    const int warp_global = blockIdx.x * (TPB_T / 32) + (threadIdx.x >> 5);

    float acc[N_BASIS];
    #pragma unroll
    for (int j = 0; j < N_BASIS; j++) acc[j] = 0.f;
    int cur = -1;

    float4 vreg[2][9];
    int4   lgreg[2], sgreg[2];

    for (int wc = warp_global; wc < NWC; wc += NWARPS_T) {
        const int base = wc * WCHUNK;
        const int np = (N_TRIPLES - base) >= WCHUNK ? 4 : 2;   // 4M%512=256 -> 2 passes

        // preload pass 0
        {
            const float4* src = tb4 + (size_t)base * 9 / 4;
            #pragma unroll
            for (int k = 0; k < 9; k++) vreg[0][k] = src[lane + 32 * k];
            lgreg[0] = lg4[base / 4 + lane];
            sgreg[0] = sg4[base / 4 + lane];
        }

        #pragma unroll
        for (int s = 0; s < 4; s++) {
            if (s >= np) break;
            const int nb = s & 1, nn = nb ^ 1;

            // issue next pass's loads (overlap with STS wait + compute)
            if (s + 1 < np) {
                const int nbase = base + (s + 1) * 128;
                const float4* src = tb4 + (size_t)nbase * 9 / 4;
                #pragma unroll
                for (int k = 0; k < 9; k++) vreg[nn][k] = src[lane + 32 * k];
                lgreg[nn] = lg4[nbase / 4 + lane];
                sgreg[nn] = sg4[nbase / 4 + lane];
            }

            __syncwarp();
            #pragma unroll
            for (int k = 0; k < 9; k++)
                reinterpret_cast<float4*>(slot)[lane + 32 * k] = vreg[nb][k];
            __syncwarp();

            // scattered atom-index gathers (L2-resident graph_dst)
            int ei[4], sv[4];
            ei[0] = __ldg(graph_dst + lgreg[nb].x);
            ei[1] = __ldg(graph_dst + lgreg[nb].y);
            ei[2] = __ldg(graph_dst + lgreg[nb].z);
            ei[3] = __ldg(graph_dst + lgreg[nb].w);
            sv[0] = sgreg[nb].x; sv[1] = sgreg[nb].y;
            sv[2] = sgreg[nb].z; sv[3] = sgreg[nb].w;

            const float* myv = slot + lane * 36;
            #pragma unroll
            for (int t = 0; t < 4; t++) {
                const int e = sv[t];
                if (e != cur) {
                    if (cur >= 0) {
                        float* dst = g_new_bonds + (size_t)cur * N_BASIS;
                        #pragma unroll
                        for (int j = 0; j < N_BASIS; j++) atomicAdd(dst + j, acc[j]);
                        #pragma unroll
                        for (int j = 0; j < N_BASIS; j++) acc[j] = 0.f;
                    }
                    cur = e;
                }
                const float* arow = s_atoms + ei[t] * N_BASIS;
                #pragma unroll
                for (int j = 0; j < N_BASIS; j++)
                    acc[j] = fmaf(myv[t * 9 + j], arow[j], acc[j]);
            }
        }
    }

    // final flush
    if (cur >= 0) {
        float* dst = g_new_bonds + (size_t)cur * N_BASIS;
        #pragma unroll
        for (int j = 0; j < N_BASIS; j++) atomicAdd(dst + j, acc[j]);
    }
}

// ---------------------------------------------------------------------------
// Kernel 3: out = edge_feat + silu(nb@W_gate+b_gate)*sigmoid(nb@W_sig+b_sig)
// (unchanged persistent version)
// ---------------------------------------------------------------------------
#define E_TILE   64
#define NB_TILE  (E_TILE * N_BASIS)            // 576 floats
#define N_TILES  (N_EDGES / E_TILE)            // 3125
#define MLP_GRID 1184                          // 8 blocks/SM * 148

__global__ __launch_bounds__(D_EDGE) void mlp_kernel(
    const float* __restrict__ edge_feat,
    const float* __restrict__ W_gate, const float* __restrict__ b_gate,
    const float* __restrict__ W_sig,  const float* __restrict__ b_sig,
    float* __restrict__ out) {

    __shared__ float s_nb[NB_TILE];

    const int j = threadIdx.x;

    float wg[N_BASIS], ws[N_BASIS];
    #pragma unroll
    for (int k = 0; k < N_BASIS; k++) {
        wg[k] = W_gate[k * D_EDGE + j];
        ws[k] = W_sig [k * D_EDGE + j];
    }
    const float bg = b_gate[j];
    const float bs = b_sig[j];

    for (int tile = blockIdx.x; tile < N_TILES; tile += MLP_GRID) {
        const int e0 = tile * E_TILE;

        __syncthreads();
        const float* nb_src = g_new_bonds + (size_t)e0 * N_BASIS;
        #pragma unroll
        for (int i = j; i < NB_TILE; i += D_EDGE)
            s_nb[i] = nb_src[i];
        __syncthreads();

        #pragma unroll 2
        for (int e = 0; e < E_TILE; e += 2) {
            const float* nb0 = s_nb + e * N_BASIS;
            const float* nb1 = nb0 + N_BASIS;

            size_t idx0 = (size_t)(e0 + e) * D_EDGE + j;
            size_t idx1 = idx0 + D_EDGE;
            float ef0 = edge_feat[idx0];
            float ef1 = edge_feat[idx1];

            float g0 = bg, s0 = bs, g1 = bg, s1 = bs;
            #pragma unroll
            for (int k = 0; k < N_BASIS; k++) {
                float n0 = nb0[k], n1 = nb1[k];
                g0 = fmaf(n0, wg[k], g0);
                s0 = fmaf(n0, ws[k], s0);
                g1 = fmaf(n1, wg[k], g1);
                s1 = fmaf(n1, ws[k], s1);
            }
            float sg0 = 1.f / (1.f + __expf(-g0));
            float ss0 = 1.f / (1.f + __expf(-s0));
            float sg1 = 1.f / (1.f + __expf(-g1));
            float ss1 = 1.f / (1.f + __expf(-s1));
            out[idx0] = ef0 + g0 * sg0 * ss0;
            out[idx1] = ef1 + g1 * sg1 * ss1;
        }
    }
}

// ---------------------------------------------------------------------------
// Launch
// ---------------------------------------------------------------------------
extern "C" void kernel_launch(void* const* d_in, const int* in_sizes, int n_in,
                              void* d_out, int out_size) {
    const float* node_feat   = (const float*)d_in[0];
    const float* edge_feat   = (const float*)d_in[1];
    const float* three_basis = (const float*)d_in[2];
    const float* W_atom      = (const float*)d_in[4];
    const float* b_atom      = (const float*)d_in[5];
    const float* W_gate      = (const float*)d_in[6];
    const float* b_gate      = (const float*)d_in[7];
    const float* W_sig       = (const float*)d_in[8];
    const float* b_sig       = (const float*)d_in[9];
    const int*   graph_dst   = (const int*)d_in[10];
    const int*   lg_dst      = (const int*)d_in[12];
    const int*   seg_ids     = (const int*)d_in[13];
    float*       out         = (float*)d_out;

    cudaFuncSetAttribute(triples_kernel,
                         cudaFuncAttributeMaxDynamicSharedMemorySize, SMEM_T_BYTES);

    zero_bonds_kernel<<<(450000 + 255) / 256, 256>>>();
    atoms_kernel<<<(N_ATOMS * N_BASIS + 255) / 256, 256>>>(node_feat, W_atom, b_atom);
    triples_kernel<<<GRID_T, TPB_T, SMEM_T_BYTES>>>(three_basis, graph_dst, lg_dst, seg_ids);
    mlp_kernel<<<MLP_GRID, D_EDGE>>>(edge_feat, W_gate, b_gate, W_sig, b_sig, out);
}